// round 9
// baseline (speedup 1.0000x reference)
#include <cuda_runtime.h>

#define THREADS  256
#define WPB      8          // warps per block; 1 row per warp
#define RPB      8          // rows per block
#define NTERMS   16
#define NBUCKETS 64
#define ROWF     512        // floats per row
#define ROWB     2048       // bytes per row

// Buckets padded to one 128-B L2 line each: [b][0]=sum, [b][1]=cnt.
// Zero at module load; finalizing block restores zeros each launch.
__device__ double   g_acc[NBUCKETS][16];
__device__ unsigned g_ticket;
__device__ int      g_flag32;   // 1 => target buffer is int32 (jax demoted)

// C = 255*ln2 + lgamma(256) - 256*ln(2*pi)
#define LOSS_C 867.968103160394f

__device__ __forceinline__ float dot4(float4 a, float4 b) {
    return a.x*b.x + a.y*b.y + a.z*b.z + a.w*b.w;
}
__device__ __forceinline__ unsigned su32(const void* p) {
    return (unsigned)__cvta_generic_to_shared(p);
}
__device__ __forceinline__ void cp16(unsigned dst, const void* src) {
    asm volatile("cp.async.cg.shared.global [%0], [%1], 16;"
                 :: "r"(dst), "l"(src) : "memory");
}
__device__ __forceinline__ void red_add_release_f64(double* p, double v) {
    asm volatile("red.add.release.gpu.global.f64 [%0], %1;"
                 :: "l"(p), "d"(v) : "memory");
}
__device__ __forceinline__ unsigned atom_add_acqrel_u32(unsigned* p, unsigned v) {
    unsigned r;
    asm volatile("atom.add.acq_rel.gpu.global.u32 %0, [%1], %2;"
                 : "=r"(r) : "l"(p), "r"(v) : "memory");
    return r;
}
__device__ __forceinline__ double ld_cg_f64(const double* p) {
    double r;
    asm volatile("ld.global.cg.f64 %0, [%1];" : "=d"(r) : "l"(p) : "memory");
    return r;
}
__device__ __forceinline__ void st_cg_f64(double* p, double v) {
    asm volatile("st.global.cg.f64 [%0], %1;" :: "l"(p), "d"(v) : "memory");
}

// Detect whether target buffer is int64 or int32. Reads first n/2 int64 words
// = first n*4 bytes, in-bounds for both layouts.
__global__ void nll_detect(const long long* __restrict__ t64, int n_half, long long vocab) {
    int i = blockIdx.x * blockDim.x + threadIdx.x;
    if (i < n_half) {
        long long v = t64[i];
        if (v < 0 || v >= vocab) g_flag32 = 1;   // all writers store 1: race-free
    }
}

__global__ void __launch_bounds__(THREADS)
nll_main(const float* __restrict__ preds,
         const void*  __restrict__ target,
         const float* __restrict__ emb,
         float* __restrict__ out, int out_size, int n)
{
    __shared__ alignas(16) float s_preds[RPB * ROWF];   // 16 KB
    __shared__ alignas(16) float s_emb[RPB * ROWF];     // 16 KB
    __shared__ int      s_tgt[RPB];
    __shared__ float    sh_loss[WPB], sh_cnt[WPB];
    __shared__ unsigned s_tkt;

    int tid  = threadIdx.x;
    int lane = tid & 31;
    int w    = tid >> 5;
    int row0 = blockIdx.x * RPB;
    int nrows = n - row0; if (nrows > RPB) nrows = RPB;
    int flag = g_flag32;   // broadcast load; overlaps with preds issue below

    // ---- preds: issue 16 KB of cp.async immediately (no dependencies) ----
    {
        const char* gp = (const char*)(preds + (size_t)row0 * ROWF);
        unsigned    sp = su32(s_preds);
        int nchunk = nrows * (ROWB / 16);
        #pragma unroll
        for (int k = 0; k < 4; k++) {
            int c = tid + k * THREADS;
            if (c < nchunk) cp16(sp + (unsigned)c * 16, gp + (size_t)c * 16);
        }
    }

    // ---- targets: one hop, 8 parallel loads ----
    if (tid < RPB) {
        int r = row0 + tid;
        int t = 1;   // PAD default (valid emb row, contributes nothing)
        if (r < n) t = flag ? ((const int*)target)[r]
                            : (int)((const long long*)target)[r];
        s_tgt[tid] = t;
    }
    __syncthreads();

    // ---- emb gather: warp w copies its row (2 KB) via 4 cp.async/lane ----
    int t = s_tgt[w];
    if (w < nrows) {
        const char* ge = (const char*)(emb + (size_t)t * ROWF);
        unsigned    se = su32(s_emb) + (unsigned)w * ROWB;
        #pragma unroll
        for (int k = 0; k < 4; k++) {
            int c = lane + k * 32;
            cp16(se + (unsigned)c * 16, ge + (size_t)c * 16);
        }
    }
    asm volatile("cp.async.commit_group;" ::: "memory");
    asm volatile("cp.async.wait_group 0;" ::: "memory");
    __syncthreads();

    // ---- compute: warp w reduces row w from smem ----
    const float4* p4 = reinterpret_cast<const float4*>(s_preds) + w * (ROWF/4) + lane;
    const float4* e4 = reinterpret_cast<const float4*>(s_emb)   + w * (ROWF/4) + lane;
    float ss = 0.0f, dt = 0.0f;
    #pragma unroll
    for (int k = 0; k < 4; k++) {
        float4 a = p4[k * 32];
        float4 b = e4[k * 32];
        ss += dot4(a, a);
        dt += dot4(a, b);
    }
    #pragma unroll
    for (int o = 16; o > 0; o >>= 1) {
        ss += __shfl_down_sync(0xffffffffu, ss, o);
        dt += __shfl_down_sync(0xffffffffu, dt, o);
    }

    float loss = 0.0f, cnt = 0.0f;
    if (lane == 0 && w < nrows && t != 1) {   // PAD_ID == 1
        float z = sqrtf(ss);
        float x = 0.25f * ss;
        // S = sum_j x^j / (j! * (256)_j); x ~ 128 => converged well before j=16.
        float S = 1.0f, term = 1.0f;
        #pragma unroll
        for (int j = 1; j < NTERMS; j++) {
            term *= x * (1.0f / ((float)j * (255.0f + (float)j)));
            S += term;
        }
        loss = logf(S) - z - dt - LOSS_C;
        cnt  = 1.0f;
    }
    if (lane == 0) { sh_loss[w] = loss; sh_cnt[w] = cnt; }
    __syncthreads();

    // ---- block reduce: 2 global reds + 1 ticket per block ----
    if (tid == 0) {
        float L = 0.0f, C = 0.0f;
        #pragma unroll
        for (int i = 0; i < WPB; i++) { L += sh_loss[i]; C += sh_cnt[i]; }
        int b = blockIdx.x & (NBUCKETS - 1);
        red_add_release_f64(&g_acc[b][0], (double)L);
        red_add_release_f64(&g_acc[b][1], (double)C);
        s_tkt = atom_add_acqrel_u32(&g_ticket, 1u);
    }
    __syncthreads();

    // ---- last block finalizes + resets state ----
    if (s_tkt == gridDim.x - 1) {
        double s = 0.0, c = 0.0;
        if (tid < NBUCKETS) {
            s = ld_cg_f64(&g_acc[tid][0]);
            c = ld_cg_f64(&g_acc[tid][1]);
        }
        #pragma unroll
        for (int o = 16; o > 0; o >>= 1) {
            s += __shfl_down_sync(0xffffffffu, s, o);
            c += __shfl_down_sync(0xffffffffu, c, o);
        }
        __shared__ double sh_s[2], sh_c[2];
        if (tid < NBUCKETS && lane == 0) { sh_s[tid >> 5] = s; sh_c[tid >> 5] = c; }
        __syncthreads();
        if (tid == 0) {
            float r = (float)((sh_s[0] + sh_s[1]) / (sh_c[0] + sh_c[1]));
            for (int i = 0; i < out_size; i++) out[i] = r;
            g_ticket = 0u;
            g_flag32 = 0;
        }
        if (tid < NBUCKETS) {
            st_cg_f64(&g_acc[tid][0], 0.0);
            st_cg_f64(&g_acc[tid][1], 0.0);
        }
    }
}

extern "C" void kernel_launch(void* const* d_in, const int* in_sizes, int n_in,
                              void* d_out, int out_size) {
    const float* preds  = (const float*)d_in[0];
    const void*  target = d_in[1];
    const float* emb    = (const float*)d_in[2];
    int n = in_sizes[1];                              // B*S rows
    long long vocab = (long long)(in_sizes[2] / 512); // rows of emb table

    int nd = n / 2;
    nll_detect<<<(nd + 255) / 256, 256>>>((const long long*)target, nd, vocab);
    int blocks = (n + RPB - 1) / RPB;
    nll_main<<<blocks, THREADS>>>(preds, target, emb, (float*)d_out, out_size, n);
}

// round 10
// speedup vs baseline: 1.0043x; 1.0043x over previous
#include <cuda_runtime.h>

#define THREADS  256
#define WPB      8          // warps per block; 1 row per warp
#define RPB      8
#define NTERMS   16
#define NBUCKETS 64
#define ROWF     512        // floats per row
#define ROWB     2048       // bytes per row

// Buckets padded to one 128-B L2 line each: [b][0]=sum, [b][1]=cnt.
// Zero at module load; finalizing block restores zeros each launch.
__device__ double   g_acc[NBUCKETS][16];
__device__ unsigned g_ticket;
__device__ int      g_flag32;   // 1 => target buffer is int32 (jax demoted)

// C = 255*ln2 + lgamma(256) - 256*ln(2*pi)
#define LOSS_C 867.968103160394f

__device__ __forceinline__ float dot4(float4 a, float4 b) {
    return a.x*b.x + a.y*b.y + a.z*b.z + a.w*b.w;
}
__device__ __forceinline__ unsigned su32(const void* p) {
    return (unsigned)__cvta_generic_to_shared(p);
}
__device__ __forceinline__ void cp16(unsigned dst, const void* src) {
    asm volatile("cp.async.cg.shared.global [%0], [%1], 16;"
                 :: "r"(dst), "l"(src) : "memory");
}
__device__ __forceinline__ void red_add_release_f64(double* p, double v) {
    asm volatile("red.add.release.gpu.global.f64 [%0], %1;"
                 :: "l"(p), "d"(v) : "memory");
}
__device__ __forceinline__ unsigned atom_add_acqrel_u32(unsigned* p, unsigned v) {
    unsigned r;
    asm volatile("atom.add.acq_rel.gpu.global.u32 %0, [%1], %2;"
                 : "=r"(r) : "l"(p), "r"(v) : "memory");
    return r;
}
__device__ __forceinline__ double ld_cg_f64(const double* p) {
    double r;
    asm volatile("ld.global.cg.f64 %0, [%1];" : "=d"(r) : "l"(p) : "memory");
    return r;
}
__device__ __forceinline__ void st_cg_f64(double* p, double v) {
    asm volatile("st.global.cg.f64 [%0], %1;" :: "l"(p), "d"(v) : "memory");
}

// Dtype detect, 1 block: scan first 256 int64 words (= first 512 int32 slots).
// If the buffer is int32, a word only looks like a valid int64 target when its
// high slot is exactly 0 (p ~ 2e-5); 256 words make a miss practically
// impossible. All in-bounds for both layouts.
__global__ void nll_detect(const long long* __restrict__ t64, int n_half, long long vocab) {
    int i = threadIdx.x;
    if (i < n_half && i < 256) {
        long long v = t64[i];
        if (v < 0 || v >= vocab) g_flag32 = 1;   // all writers store 1: race-free
    }
}

__global__ void __launch_bounds__(THREADS)
nll_main(const float* __restrict__ preds,
         const void*  __restrict__ target,
         const float* __restrict__ emb,
         float* __restrict__ out, int out_size, int n)
{
    __shared__ alignas(16) float s_emb[RPB * ROWF];   // 16 KB
    __shared__ float    sh_loss[WPB], sh_cnt[WPB];
    __shared__ unsigned s_tkt;

    int tid  = threadIdx.x;
    int lane = tid & 31;
    int w    = tid >> 5;
    int row  = blockIdx.x * RPB + w;
    int rowc = row < n ? row : 0;
    int flag = g_flag32;                 // one L2 broadcast, overlaps loads

    // ---- warp-autonomous pipeline: no inter-warp coupling ----
    // lane 0: target load (the only serial hop)
    long long t_l = 1;
    if (lane == 0 && row < n) {
        t_l = flag ? (long long)((const int*)target)[row]
                   : ((const long long*)target)[row];
    }

    // preds to registers: 4 independent LDG.128 per lane, in flight now
    const float4* p = reinterpret_cast<const float4*>(preds) + (size_t)rowc * ROWF/4 + lane;
    float4 a0 = p[0], a1 = p[32], a2 = p[64], a3 = p[96];

    long long t = __shfl_sync(0xffffffffu, t_l, 0);
    if (row >= n) t = 1;                 // PAD => contributes nothing

    // emb gather via cp.async; each lane copies chunks lane+32k and will
    // consume exactly those chunks => per-thread wait, no barrier needed.
    const char* ge = (const char*)(emb + (size_t)t * ROWF);
    unsigned    se = su32(s_emb) + (unsigned)w * ROWB;
    #pragma unroll
    for (int k = 0; k < 4; k++) {
        unsigned c = (unsigned)lane + 32u * k;
        cp16(se + c * 16u, ge + (size_t)c * 16u);
    }
    asm volatile("cp.async.commit_group;" ::: "memory");
    asm volatile("cp.async.wait_group 0;" ::: "memory");

    const float4* e4 = reinterpret_cast<const float4*>(s_emb) + w * (ROWF/4) + lane;
    float4 b0 = e4[0], b1 = e4[32], b2 = e4[64], b3 = e4[96];

    float ss = dot4(a0,a0) + dot4(a1,a1) + dot4(a2,a2) + dot4(a3,a3);
    float dt = dot4(a0,b0) + dot4(a1,b1) + dot4(a2,b2) + dot4(a3,b3);

    #pragma unroll
    for (int o = 16; o > 0; o >>= 1) {
        ss += __shfl_down_sync(0xffffffffu, ss, o);
        dt += __shfl_down_sync(0xffffffffu, dt, o);
    }

    float loss = 0.0f, cnt = 0.0f;
    if (lane == 0 && t != 1) {   // PAD_ID == 1
        float z = sqrtf(ss);
        float x = 0.25f * ss;
        // S = sum_j x^j / (j! * (256)_j); x ~ 128 => converged well before j=16.
        float S = 1.0f, term = 1.0f;
        #pragma unroll
        for (int j = 1; j < NTERMS; j++) {
            term *= x * (1.0f / ((float)j * (255.0f + (float)j)));
            S += term;
        }
        loss = logf(S) - z - dt - LOSS_C;
        cnt  = 1.0f;
    }
    if (lane == 0) { sh_loss[w] = loss; sh_cnt[w] = cnt; }
    __syncthreads();

    // ---- block reduce: 2 global reds + 1 ticket per block ----
    if (tid == 0) {
        float L = 0.0f, C = 0.0f;
        #pragma unroll
        for (int i = 0; i < WPB; i++) { L += sh_loss[i]; C += sh_cnt[i]; }
        int b = blockIdx.x & (NBUCKETS - 1);
        red_add_release_f64(&g_acc[b][0], (double)L);
        red_add_release_f64(&g_acc[b][1], (double)C);
        s_tkt = atom_add_acqrel_u32(&g_ticket, 1u);
    }
    __syncthreads();

    // ---- last block finalizes + resets state ----
    if (s_tkt == gridDim.x - 1) {
        double s = 0.0, c = 0.0;
        if (tid < NBUCKETS) {
            s = ld_cg_f64(&g_acc[tid][0]);
            c = ld_cg_f64(&g_acc[tid][1]);
        }
        #pragma unroll
        for (int o = 16; o > 0; o >>= 1) {
            s += __shfl_down_sync(0xffffffffu, s, o);
            c += __shfl_down_sync(0xffffffffu, c, o);
        }
        __shared__ double sh_s[2], sh_c[2];
        if (tid < NBUCKETS && lane == 0) { sh_s[tid >> 5] = s; sh_c[tid >> 5] = c; }
        __syncthreads();
        if (tid == 0) {
            float r = (float)((sh_s[0] + sh_s[1]) / (sh_c[0] + sh_c[1]));
            for (int i = 0; i < out_size; i++) out[i] = r;
            g_ticket = 0u;
            g_flag32 = 0;
        }
        if (tid < NBUCKETS) {
            st_cg_f64(&g_acc[tid][0], 0.0);
            st_cg_f64(&g_acc[tid][1], 0.0);
        }
    }
}

extern "C" void kernel_launch(void* const* d_in, const int* in_sizes, int n_in,
                              void* d_out, int out_size) {
    const float* preds  = (const float*)d_in[0];
    const void*  target = d_in[1];
    const float* emb    = (const float*)d_in[2];
    int n = in_sizes[1];                              // B*S rows
    long long vocab = (long long)(in_sizes[2] / 512); // rows of emb table

    int nd = n / 2;
    nll_detect<<<1, 256>>>((const long long*)target, nd, vocab);
    int blocks = (n + RPB - 1) / RPB;
    nll_main<<<blocks, THREADS>>>(preds, target, emb, (float*)d_out, out_size, n);
}

// round 11
// speedup vs baseline: 1.1654x; 1.1604x over previous
#include <cuda_runtime.h>

#define THREADS  256
#define WPB      8          // warps per block; 1 row per warp
#define RPB      8
#define NTERMS   16
#define NBUCKETS 64
#define ROWF     512        // floats per row
#define ROWB     2048       // bytes per row

// Buckets padded to one 128-B L2 line each: [b][0]=sum, [b][1]=cnt.
// Zero at module load; finalizing block restores zeros each launch.
__device__ double   g_acc[NBUCKETS][16];
__device__ unsigned g_ticket;

// C = 255*ln2 + lgamma(256) - 256*ln(2*pi)
#define LOSS_C 867.968103160394f

__device__ __forceinline__ float dot4(float4 a, float4 b) {
    return a.x*b.x + a.y*b.y + a.z*b.z + a.w*b.w;
}
__device__ __forceinline__ unsigned su32(const void* p) {
    return (unsigned)__cvta_generic_to_shared(p);
}
__device__ __forceinline__ void cp16(unsigned dst, const void* src) {
    asm volatile("cp.async.cg.shared.global [%0], [%1], 16;"
                 :: "r"(dst), "l"(src) : "memory");
}
__device__ __forceinline__ void red_add_release_f64(double* p, double v) {
    asm volatile("red.add.release.gpu.global.f64 [%0], %1;"
                 :: "l"(p), "d"(v) : "memory");
}
__device__ __forceinline__ unsigned atom_add_acqrel_u32(unsigned* p, unsigned v) {
    unsigned r;
    asm volatile("atom.add.acq_rel.gpu.global.u32 %0, [%1], %2;"
                 : "=r"(r) : "l"(p), "r"(v) : "memory");
    return r;
}
__device__ __forceinline__ double ld_cg_f64(const double* p) {
    double r;
    asm volatile("ld.global.cg.f64 %0, [%1];" : "=d"(r) : "l"(p) : "memory");
    return r;
}
__device__ __forceinline__ void st_cg_f64(double* p, double v) {
    asm volatile("st.global.cg.f64 [%0], %1;" :: "l"(p), "d"(v) : "memory");
}

__global__ void __launch_bounds__(THREADS)
nll_main(const float* __restrict__ preds,
         const void*  __restrict__ target,
         const float* __restrict__ emb,
         float* __restrict__ out, int out_size, int n, long long vocab)
{
    __shared__ alignas(16) float s_emb[RPB * ROWF];   // 16 KB
    __shared__ float    sh_loss[WPB], sh_cnt[WPB];
    __shared__ unsigned s_tkt;

    int tid  = threadIdx.x;
    int lane = tid & 31;
    int w    = tid >> 5;
    int row  = blockIdx.x * RPB + w;
    int rowc = row < n ? row : 0;

    // ---- inline dtype detection: every warp reads the SAME first 32 int64
    // words (256 B, L2-broadcast; in-bounds for both layouts when n >= 64).
    // int64 buffer: all values in [0,vocab) -> flag 0. int32 buffer: word i
    // valid only if tgt[2i+1]==0 (p~2e-5); all-32 valid is impossible.
    long long dv = ((const long long*)target)[lane];
    unsigned badm = __ballot_sync(0xffffffffu, dv < 0 || dv >= vocab);
    int flag32 = (badm != 0);

    // ---- warp-autonomous pipeline ----
    long long t_l = 1;
    if (lane == 0 && row < n) {
        t_l = flag32 ? (long long)((const int*)target)[row]
                     : ((const long long*)target)[row];
    }

    // preds to registers: 4 independent LDG.128 per lane, in flight now
    const float4* p = reinterpret_cast<const float4*>(preds) + (size_t)rowc * ROWF/4 + lane;
    float4 a0 = p[0], a1 = p[32], a2 = p[64], a3 = p[96];

    long long t = __shfl_sync(0xffffffffu, t_l, 0);
    if (row >= n) t = 1;                 // PAD => contributes nothing

    // emb gather via cp.async; each lane copies chunks lane+32k and consumes
    // exactly those chunks => per-thread wait, no barrier needed.
    const char* ge = (const char*)(emb + (size_t)t * ROWF);
    unsigned    se = su32(s_emb) + (unsigned)w * ROWB;
    #pragma unroll
    for (int k = 0; k < 4; k++) {
        unsigned c = (unsigned)lane + 32u * k;
        cp16(se + c * 16u, ge + (size_t)c * 16u);
    }
    asm volatile("cp.async.commit_group;" ::: "memory");
    asm volatile("cp.async.wait_group 0;" ::: "memory");

    const float4* e4 = reinterpret_cast<const float4*>(s_emb) + w * (ROWF/4) + lane;
    float4 b0 = e4[0], b1 = e4[32], b2 = e4[64], b3 = e4[96];

    float ss = dot4(a0,a0) + dot4(a1,a1) + dot4(a2,a2) + dot4(a3,a3);
    float dt = dot4(a0,b0) + dot4(a1,b1) + dot4(a2,b2) + dot4(a3,b3);

    #pragma unroll
    for (int o = 16; o > 0; o >>= 1) {
        ss += __shfl_down_sync(0xffffffffu, ss, o);
        dt += __shfl_down_sync(0xffffffffu, dt, o);
    }

    float loss = 0.0f, cnt = 0.0f;
    if (lane == 0 && t != 1) {   // PAD_ID == 1
        float z = sqrtf(ss);
        float x = 0.25f * ss;
        // S = sum_j x^j / (j! * (256)_j); x ~ 128 => converged well before j=16.
        float S = 1.0f, term = 1.0f;
        #pragma unroll
        for (int j = 1; j < NTERMS; j++) {
            term *= x * (1.0f / ((float)j * (255.0f + (float)j)));
            S += term;
        }
        loss = logf(S) - z - dt - LOSS_C;
        cnt  = 1.0f;
    }
    if (lane == 0) { sh_loss[w] = loss; sh_cnt[w] = cnt; }
    __syncthreads();

    // ---- block reduce: 2 global reds + 1 ticket per block ----
    if (tid == 0) {
        float L = 0.0f, C = 0.0f;
        #pragma unroll
        for (int i = 0; i < WPB; i++) { L += sh_loss[i]; C += sh_cnt[i]; }
        int b = blockIdx.x & (NBUCKETS - 1);
        red_add_release_f64(&g_acc[b][0], (double)L);
        red_add_release_f64(&g_acc[b][1], (double)C);
        s_tkt = atom_add_acqrel_u32(&g_ticket, 1u);
    }
    __syncthreads();

    // ---- last block finalizes + resets state ----
    if (s_tkt == gridDim.x - 1) {
        double s = 0.0, c = 0.0;
        if (tid < NBUCKETS) {
            s = ld_cg_f64(&g_acc[tid][0]);
            c = ld_cg_f64(&g_acc[tid][1]);
        }
        #pragma unroll
        for (int o = 16; o > 0; o >>= 1) {
            s += __shfl_down_sync(0xffffffffu, s, o);
            c += __shfl_down_sync(0xffffffffu, c, o);
        }
        __shared__ double sh_s[2], sh_c[2];
        if (tid < NBUCKETS && lane == 0) { sh_s[tid >> 5] = s; sh_c[tid >> 5] = c; }
        __syncthreads();
        if (tid == 0) {
            float r = (float)((sh_s[0] + sh_s[1]) / (sh_c[0] + sh_c[1]));
            for (int i = 0; i < out_size; i++) out[i] = r;
            g_ticket = 0u;
        }
        if (tid < NBUCKETS) {
            st_cg_f64(&g_acc[tid][0], 0.0);
            st_cg_f64(&g_acc[tid][1], 0.0);
        }
    }
}

extern "C" void kernel_launch(void* const* d_in, const int* in_sizes, int n_in,
                              void* d_out, int out_size) {
    const float* preds  = (const float*)d_in[0];
    const void*  target = d_in[1];
    const float* emb    = (const float*)d_in[2];
    int n = in_sizes[1];                              // B*S rows
    long long vocab = (long long)(in_sizes[2] / 512); // rows of emb table

    int blocks = (n + RPB - 1) / RPB;
    nll_main<<<blocks, THREADS>>>(preds, target, emb, (float*)d_out,
                                  out_size, n, vocab);
}